// round 1
// baseline (speedup 1.0000x reference)
#include <cuda_runtime.h>
#include <math.h>
#include <stdint.h>

// Fixed problem sizes (scratch capacity); runtime dims derived from in_sizes.
#define MAXF 4096
#define MAXN 8192

// -------- device scratch (no allocations allowed) --------
__device__ float g_wq[(size_t)MAXF * MAXF];          // quantized weights, fp32
__device__ float g_G[(size_t)MAXN * MAXF];           // GEMM output
__device__ unsigned int g_maxbits;                   // max|W| as uint bits
__device__ float g_scale;
__device__ float g_psum[8][MAXF];
__device__ float g_psq[8][MAXF];
__device__ float g_mean[MAXF];
__device__ float g_rstd[MAXF];

// -------- kernel 0: reset reduction state --------
__global__ void init_kernel() {
    if (threadIdx.x == 0) g_maxbits = 0u;
}

// -------- kernel 1: max|W| (order-independent, deterministic) --------
__global__ void maxabs_kernel(const float* __restrict__ W, int n) {
    float m = 0.f;
    for (int i = blockIdx.x * blockDim.x + threadIdx.x; i < n;
         i += gridDim.x * blockDim.x)
        m = fmaxf(m, fabsf(W[i]));
    #pragma unroll
    for (int o = 16; o > 0; o >>= 1)
        m = fmaxf(m, __shfl_xor_sync(0xffffffffu, m, o));
    if ((threadIdx.x & 31) == 0)
        atomicMax(&g_maxbits, __float_as_uint(m));  // >=0 floats: uint order == float order
}

// -------- kernel 2: scale = max|W| / (2^(wbits-1)-1) --------
__global__ void scale_kernel(const int* __restrict__ wbits) {
    float nf = (float)((1 << ((*wbits) - 1)) - 1);
    g_scale = __fdiv_rn(__uint_as_float(g_maxbits), nf);  // IEEE div regardless of fast_math
}

// -------- kernel 3: quantize weights exactly like reference --------
__global__ void quantw_kernel(const float* __restrict__ W,
                              const int* __restrict__ wbits, int n) {
    float s = g_scale;
    float nf = (float)((1 << ((*wbits) - 1)) - 1);
    for (int i = blockIdx.x * blockDim.x + threadIdx.x; i < n;
         i += gridDim.x * blockDim.x) {
        float w = W[i];
        // rintf == round-half-to-even == jnp.round; __fdiv_rn is correctly rounded
        float q = fminf(fmaxf(rintf(__fdiv_rn(w, s)), -nf), nf) * s;
        g_wq[i] = w + (q - w);   // mirror STE expression bit-for-bit
    }
}

// -------- kernel 4: fp32 SGEMM  G[N,Fout] = x[N,K] * wq[Fout,K]^T --------
// 128x128 block tile, BK=8, 256 threads, 8x8 per-thread microtile.
__global__ __launch_bounds__(256, 2)
void gemm_kernel(const float* __restrict__ A, int M, int Nc, int K) {
    __shared__ float As[8][128];
    __shared__ float Bs[8][128];

    const int tid  = threadIdx.x;
    const int arow = tid >> 1;            // 0..127
    const int acol = (tid & 1) << 2;      // 0 or 4
    const float* Ap = A    + (size_t)(blockIdx.y * 128 + arow) * K + acol;
    const float* Bp = g_wq + (size_t)(blockIdx.x * 128 + arow) * K + acol;

    const int trow = (tid >> 4) << 3;     // 0..120 step 8
    const int tcol = (tid & 15) << 3;     // 0..120 step 8

    float acc[8][8];
    #pragma unroll
    for (int i = 0; i < 8; i++)
        #pragma unroll
        for (int j = 0; j < 8; j++) acc[i][j] = 0.f;

    for (int k0 = 0; k0 < K; k0 += 8) {
        float4 av = *(const float4*)Ap;
        float4 bv = *(const float4*)Bp;
        Ap += 8; Bp += 8;
        As[acol + 0][arow] = av.x; As[acol + 1][arow] = av.y;
        As[acol + 2][arow] = av.z; As[acol + 3][arow] = av.w;
        Bs[acol + 0][arow] = bv.x; Bs[acol + 1][arow] = bv.y;
        Bs[acol + 2][arow] = bv.z; Bs[acol + 3][arow] = bv.w;
        __syncthreads();

        #pragma unroll
        for (int k = 0; k < 8; k++) {
            float ra[8], rb[8];
            *(float4*)&ra[0] = *(const float4*)&As[k][trow];
            *(float4*)&ra[4] = *(const float4*)&As[k][trow + 4];
            *(float4*)&rb[0] = *(const float4*)&Bs[k][tcol];
            *(float4*)&rb[4] = *(const float4*)&Bs[k][tcol + 4];
            #pragma unroll
            for (int i = 0; i < 8; i++)
                #pragma unroll
                for (int j = 0; j < 8; j++)
                    acc[i][j] = fmaf(ra[i], rb[j], acc[i][j]);
        }
        __syncthreads();
    }

    #pragma unroll
    for (int i = 0; i < 8; i++) {
        float* Cp = g_G + (size_t)(blockIdx.y * 128 + trow + i) * Nc
                        + blockIdx.x * 128 + tcol;
        *(float4*)&Cp[0] = *(float4*)&acc[i][0];
        *(float4*)&Cp[4] = *(float4*)&acc[i][4];
    }
}

// -------- kernel 5: per-column partial sums (deterministic two-stage) --------
__global__ void stats_kernel(int Nr, int Nc) {
    int c  = blockIdx.x * blockDim.x + threadIdx.x;   // column
    int rb = blockIdx.y;                              // row block 0..7
    int rows = Nr >> 3;
    const float* p = g_G + (size_t)(rb * rows) * Nc + c;
    float s0 = 0.f, s1 = 0.f, q0 = 0.f, q1 = 0.f;
    for (int r = 0; r < rows; r += 2) {
        float v0 = p[0];
        float v1 = p[Nc];
        p += 2 * (size_t)Nc;
        s0 += v0; q0 = fmaf(v0, v0, q0);
        s1 += v1; q1 = fmaf(v1, v1, q1);
    }
    g_psum[rb][c] = s0 + s1;
    g_psq[rb][c]  = q0 + q1;
}

// -------- kernel 6: mean / rstd per column --------
__global__ void coef_kernel(int Nr, int Nc) {
    int c = blockIdx.x * blockDim.x + threadIdx.x;
    if (c >= Nc) return;
    float s = 0.f, q = 0.f;
    #pragma unroll
    for (int i = 0; i < 8; i++) { s += g_psum[i][c]; q += g_psq[i][c]; }
    float mean = s / (float)Nr;   // Nr is 2^k: exact
    float ex2  = q / (float)Nr;
    float var  = ex2 - mean * mean;
    g_mean[c] = mean;
    g_rstd[c] = (float)(1.0 / sqrt((double)var + 1e-5));  // only Nc fp64 ops
}

// -------- kernel 7: fused BN + activation quantization --------
__global__ void bnq_kernel(const float* __restrict__ gamma,
                           const float* __restrict__ beta,
                           const int* __restrict__ abits,
                           float* __restrict__ out, int total, int Nc) {
    float na = (float)((1 << (*abits)) - 1);
    for (int i = blockIdx.x * blockDim.x + threadIdx.x; i < total;
         i += gridDim.x * blockDim.x) {
        int c = i % Nc;
        float g = g_G[i];
        float y = gamma[c] * (g - g_mean[c]) * g_rstd[c] + beta[c];
        float yc = fminf(fmaxf(y, 0.f), 1.f);
        float q = __fdiv_rn(rintf(yc * na), na);  // ties-to-even, exact div
        out[i] = yc + (q - yc);                   // mirror STE expression
    }
}

extern "C" void kernel_launch(void* const* d_in, const int* in_sizes, int n_in,
                              void* d_out, int out_size) {
    const float* x     = (const float*)d_in[0];
    const float* W     = (const float*)d_in[1];
    const float* gamma = (const float*)d_in[2];
    const float* beta  = (const float*)d_in[3];
    const int*   wbits = (const int*)d_in[4];
    const int*   abits = (const int*)d_in[5];

    int Fout = in_sizes[2];                 // gamma length
    int Fin  = in_sizes[1] / Fout;          // W is [Fout, Fin]
    int N    = in_sizes[0] / Fin;           // x is [N, Fin]
    int wn   = in_sizes[1];
    int total = N * Fout;

    init_kernel<<<1, 32>>>();
    maxabs_kernel<<<256, 256>>>(W, wn);
    scale_kernel<<<1, 1>>>(wbits);
    quantw_kernel<<<256, 256>>>(W, wbits, wn);

    dim3 gg(Fout / 128, N / 128);
    gemm_kernel<<<gg, 256>>>(x, N, Fout, Fin);

    dim3 gs(Fout / 256, 8);
    stats_kernel<<<gs, 256>>>(N, Fout);
    coef_kernel<<<(Fout + 255) / 256, 256>>>(N, Fout);

    bnq_kernel<<<2048, 256>>>(gamma, beta, abits, (float*)d_out, total, Fout);
}

// round 4
// speedup vs baseline: 3.0905x; 3.0905x over previous
#include <cuda_runtime.h>
#include <cuda_bf16.h>
#include <math.h>
#include <stdint.h>

// Fixed problem shape (verified R1: x[8192,4096], W[4096,4096])
#define K_IN 4096
#define NROW 8192
#define FOUT 4096

#define BM 128
#define BN 128
#define BK 16
#define NCH (K_IN / BK)       // 256
#define MT (NROW / BM)        // 64
#define NT (FOUT / BN)        // 32
#define SSTRIDE 24            // smem row stride in bf16 (48B: 16B-aligned, conflict-free)

// ---------------- device scratch ----------------
__device__ __nv_bfloat16 g_Ap[(size_t)NROW * (2 * K_IN)];  // [xh | xl], row stride 2*K_IN
__device__ __nv_bfloat16 g_Bp[(size_t)FOUT * K_IN];        // integer weight codes
__device__ float g_G[(size_t)NROW * FOUT];
__device__ unsigned int g_maxbits;
__device__ float g_scale;
__device__ float g_psum[8][FOUT];
__device__ float g_psq[8][FOUT];
__device__ float g_mean[FOUT];
__device__ float g_rstd[FOUT];

// ---------------- helpers (all sm_80-era PTX: safe at compute_100) ----------------
__device__ __forceinline__ uint32_t smem_u32(const void* p) {
    return (uint32_t)__cvta_generic_to_shared(p);
}
#define CP_ASYNC16(dst, src) \
    asm volatile("cp.async.cg.shared.global [%0], [%1], 16;" :: "r"(dst), "l"(src) : "memory")
#define CP_COMMIT() asm volatile("cp.async.commit_group;" ::: "memory")
#define CP_WAIT1()  asm volatile("cp.async.wait_group 1;" ::: "memory")
#define CP_WAIT0()  asm volatile("cp.async.wait_group 0;" ::: "memory")

__device__ __forceinline__ void ldm_x4(uint32_t* r, uint32_t addr) {
    asm volatile("ldmatrix.sync.aligned.m8n8.x4.shared.b16 {%0,%1,%2,%3}, [%4];"
                 : "=r"(r[0]), "=r"(r[1]), "=r"(r[2]), "=r"(r[3]) : "r"(addr));
}
__device__ __forceinline__ void ldm_x2(uint32_t* r, uint32_t addr) {
    asm volatile("ldmatrix.sync.aligned.m8n8.x2.shared.b16 {%0,%1}, [%2];"
                 : "=r"(r[0]), "=r"(r[1]) : "r"(addr));
}
__device__ __forceinline__ void mma_bf16(float* d, const uint32_t* a, const uint32_t* b) {
    asm volatile(
        "mma.sync.aligned.m16n8k16.row.col.f32.bf16.bf16.f32 "
        "{%0,%1,%2,%3}, {%4,%5,%6,%7}, {%8,%9}, {%0,%1,%2,%3};"
        : "+f"(d[0]), "+f"(d[1]), "+f"(d[2]), "+f"(d[3])
        : "r"(a[0]), "r"(a[1]), "r"(a[2]), "r"(a[3]), "r"(b[0]), "r"(b[1]));
}

// ---------------- small kernels ----------------
__global__ void init_kernel() { if (threadIdx.x == 0) g_maxbits = 0u; }

__global__ void maxabs_kernel(const float* __restrict__ W, int n) {
    float m = 0.f;
    for (int i = blockIdx.x * blockDim.x + threadIdx.x; i < n;
         i += gridDim.x * blockDim.x)
        m = fmaxf(m, fabsf(W[i]));
    #pragma unroll
    for (int o = 16; o > 0; o >>= 1)
        m = fmaxf(m, __shfl_xor_sync(0xffffffffu, m, o));
    if ((threadIdx.x & 31) == 0)
        atomicMax(&g_maxbits, __float_as_uint(m));
}

__global__ void scale_kernel(const int* __restrict__ wbits) {
    float nf = (float)((1 << ((*wbits) - 1)) - 1);
    g_scale = __fdiv_rn(__uint_as_float(g_maxbits), nf);
}

// W -> integer codes m (exact in bf16)
__global__ void quantm_kernel(const float* __restrict__ W,
                              const int* __restrict__ wbits) {
    float s = g_scale;
    float nf = (float)((1 << ((*wbits) - 1)) - 1);
    int t = blockIdx.x * blockDim.x + threadIdx.x;   // over FOUT*K_IN/4
    float4 w = ((const float4*)W)[t];
    float m0 = fminf(fmaxf(rintf(__fdiv_rn(w.x, s)), -nf), nf);
    float m1 = fminf(fmaxf(rintf(__fdiv_rn(w.y, s)), -nf), nf);
    float m2 = fminf(fmaxf(rintf(__fdiv_rn(w.z, s)), -nf), nf);
    float m3 = fminf(fmaxf(rintf(__fdiv_rn(w.w, s)), -nf), nf);
    __nv_bfloat162* d = (__nv_bfloat162*)&g_Bp[(size_t)t * 4];
    d[0] = __floats2bfloat162_rn(m0, m1);
    d[1] = __floats2bfloat162_rn(m2, m3);
}

// x -> [xh | xl] bf16 (row stride 2*K_IN)
__global__ void splitx_kernel(const float* __restrict__ x) {
    int t = blockIdx.x * blockDim.x + threadIdx.x;   // over NROW*K_IN/4
    float4 v = ((const float4*)x)[t];
    int row = t >> 10;                 // / (K_IN/4)
    int col = (t & 1023) << 2;
    __nv_bfloat16 h0 = __float2bfloat16_rn(v.x);
    __nv_bfloat16 h1 = __float2bfloat16_rn(v.y);
    __nv_bfloat16 h2 = __float2bfloat16_rn(v.z);
    __nv_bfloat16 h3 = __float2bfloat16_rn(v.w);
    __nv_bfloat16 l0 = __float2bfloat16_rn(v.x - __bfloat162float(h0));
    __nv_bfloat16 l1 = __float2bfloat16_rn(v.y - __bfloat162float(h1));
    __nv_bfloat16 l2 = __float2bfloat16_rn(v.z - __bfloat162float(h2));
    __nv_bfloat16 l3 = __float2bfloat16_rn(v.w - __bfloat162float(h3));
    __nv_bfloat162* dh = (__nv_bfloat162*)&g_Ap[(size_t)row * (2 * K_IN) + col];
    __nv_bfloat162* dl = (__nv_bfloat162*)&g_Ap[(size_t)row * (2 * K_IN) + K_IN + col];
    dh[0] = __nv_bfloat162{h0, h1}; dh[1] = __nv_bfloat162{h2, h3};
    dl[0] = __nv_bfloat162{l0, l1}; dl[1] = __nv_bfloat162{l2, l3};
}

// ---------------- GEMM: mma.sync bf16, 128x128 tile, cp.async double buffer ----------
__global__ void __launch_bounds__(256) gemm_mma() {
    __shared__ __nv_bfloat16 sAh[2][BM * SSTRIDE];
    __shared__ __nv_bfloat16 sAl[2][BM * SSTRIDE];
    __shared__ __nv_bfloat16 sB[2][BN * SSTRIDE];

    const int tid = threadIdx.x;
    const int wid = tid >> 5;
    const int lane = tid & 31;
    const int wm = wid & 1;          // 2 warp rows (64 rows each)
    const int wn = wid >> 1;         // 4 warp cols (32 cols each)

    const int cid = blockIdx.x;
    const int tm = cid >> 5;         // 0..63
    const int tn = cid & 31;         // 0..31

    float acc[4][4][4];
    #pragma unroll
    for (int a = 0; a < 4; a++)
        #pragma unroll
        for (int b = 0; b < 4; b++)
            #pragma unroll
            for (int c = 0; c < 4; c++) acc[a][b][c] = 0.f;

    // loader mapping: thread t -> row t/2, 16B chunk t&1 (row = 32B)
    const int lr = tid >> 1;
    const int lc = tid & 1;
    const char* gAh = (const char*)(g_Ap + (size_t)(tm * BM + lr) * (2 * K_IN)) + lc * 16;
    const char* gAl = gAh + (size_t)K_IN * 2;
    const char* gB  = (const char*)(g_Bp + (size_t)(tn * BN + lr) * K_IN) + lc * 16;
    const uint32_t dst_off = (uint32_t)(lr * SSTRIDE * 2 + lc * 16);
    const uint32_t sAh_u[2] = { smem_u32(sAh[0]), smem_u32(sAh[1]) };
    const uint32_t sAl_u[2] = { smem_u32(sAl[0]), smem_u32(sAl[1]) };
    const uint32_t sB_u[2]  = { smem_u32(sB[0]),  smem_u32(sB[1]) };

    // ldmatrix address components
    const uint32_t a_off = (uint32_t)(((wm * 64 + (lane & 15)) * SSTRIDE + (lane >> 4) * 8) * 2);
    const uint32_t b_off = (uint32_t)(((wn * 32 + (lane & 7)) * SSTRIDE + ((lane >> 3) & 1) * 8) * 2);

    // prologue: stage 0
    {
        CP_ASYNC16(sAh_u[0] + dst_off, gAh);
        CP_ASYNC16(sAl_u[0] + dst_off, gAl);
        CP_ASYNC16(sB_u[0]  + dst_off, gB);
        CP_COMMIT();
    }

    for (int i = 0; i < NCH; i++) {
        const int b = i & 1;
        if (i + 1 < NCH) {
            const int nb = (i + 1) & 1;
            const size_t ko = (size_t)(i + 1) * BK * 2;   // bytes along K
            CP_ASYNC16(sAh_u[nb] + dst_off, gAh + ko);
            CP_ASYNC16(sAl_u[nb] + dst_off, gAl + ko);
            CP_ASYNC16(sB_u[nb]  + dst_off, gB + ko);
            CP_COMMIT();
            CP_WAIT1();
        } else {
            CP_WAIT0();
        }
        __syncthreads();

        uint32_t bf[4][2];
        #pragma unroll
        for (int nt = 0; nt < 4; nt++)
            ldm_x2(bf[nt], sB_u[b] + b_off + (uint32_t)(nt * 8 * SSTRIDE * 2));

        uint32_t ah[4][4], al[4][4];
        #pragma unroll
        for (int mt = 0; mt < 4; mt++) {
            ldm_x4(ah[mt], sAh_u[b] + a_off + (uint32_t)(mt * 16 * SSTRIDE * 2));
            ldm_x4(al[mt], sAl_u[b] + a_off + (uint32_t)(mt * 16 * SSTRIDE * 2));
        }
        #pragma unroll
        for (int mt = 0; mt < 4; mt++)
            #pragma unroll
            for (int nt = 0; nt < 4; nt++) {
                mma_bf16(acc[mt][nt], ah[mt], bf[nt]);
                mma_bf16(acc[mt][nt], al[mt], bf[nt]);
            }
        __syncthreads();
    }

    // epilogue: scale by s, direct float2 stores
    const float s = g_scale;
    const int rbase = tm * BM + wm * 64 + (lane >> 2);
    const int cbase = tn * BN + wn * 32 + 2 * (lane & 3);
    #pragma unroll
    for (int mt = 0; mt < 4; mt++) {
        #pragma unroll
        for (int nt = 0; nt < 4; nt++) {
            const int rr = rbase + mt * 16;
            const int cc = cbase + nt * 8;
            float2 v0 = { acc[mt][nt][0] * s, acc[mt][nt][1] * s };
            float2 v1 = { acc[mt][nt][2] * s, acc[mt][nt][3] * s };
            *(float2*)&g_G[(size_t)rr * FOUT + cc] = v0;
            *(float2*)&g_G[(size_t)(rr + 8) * FOUT + cc] = v1;
        }
    }
}

// ---------------- stats + BN + act-quant (verified in R1) ----------------
__global__ void stats_kernel(int Nr, int Nc) {
    int c  = blockIdx.x * blockDim.x + threadIdx.x;
    int rb = blockIdx.y;
    int rows = Nr >> 3;
    const float* p = g_G + (size_t)(rb * rows) * Nc + c;
    float s0 = 0.f, s1 = 0.f, q0 = 0.f, q1 = 0.f;
    for (int r = 0; r < rows; r += 2) {
        float v0 = p[0];
        float v1 = p[Nc];
        p += 2 * (size_t)Nc;
        s0 += v0; q0 = fmaf(v0, v0, q0);
        s1 += v1; q1 = fmaf(v1, v1, q1);
    }
    g_psum[rb][c] = s0 + s1;
    g_psq[rb][c]  = q0 + q1;
}

__global__ void coef_kernel(int Nr, int Nc) {
    int c = blockIdx.x * blockDim.x + threadIdx.x;
    if (c >= Nc) return;
    float s = 0.f, q = 0.f;
    #pragma unroll
    for (int i = 0; i < 8; i++) { s += g_psum[i][c]; q += g_psq[i][c]; }
    float mean = s / (float)Nr;
    float ex2  = q / (float)Nr;
    float var  = ex2 - mean * mean;
    g_mean[c] = mean;
    g_rstd[c] = (float)(1.0 / sqrt((double)var + 1e-5));
}

__global__ void bnq_kernel(const float* __restrict__ gamma,
                           const float* __restrict__ beta,
                           const int* __restrict__ abits,
                           float* __restrict__ out, int total, int Nc) {
    float na = (float)((1 << (*abits)) - 1);
    for (int i = blockIdx.x * blockDim.x + threadIdx.x; i < total;
         i += gridDim.x * blockDim.x) {
        int c = i % Nc;
        float g = g_G[i];
        float y = gamma[c] * (g - g_mean[c]) * g_rstd[c] + beta[c];
        float yc = fminf(fmaxf(y, 0.f), 1.f);
        float q = __fdiv_rn(rintf(yc * na), na);
        out[i] = yc + (q - yc);
    }
}

// ---------------- launch ----------------
extern "C" void kernel_launch(void* const* d_in, const int* in_sizes, int n_in,
                              void* d_out, int out_size) {
    const float* x     = (const float*)d_in[0];
    const float* W     = (const float*)d_in[1];
    const float* gamma = (const float*)d_in[2];
    const float* beta  = (const float*)d_in[3];
    const int*   wbits = (const int*)d_in[4];
    const int*   abits = (const int*)d_in[5];

    init_kernel<<<1, 32>>>();
    maxabs_kernel<<<256, 256>>>(W, FOUT * K_IN);
    scale_kernel<<<1, 1>>>(wbits);
    quantm_kernel<<<(FOUT * K_IN / 4) / 256, 256>>>(W, wbits);
    splitx_kernel<<<(NROW * K_IN / 4) / 256, 256>>>(x);

    gemm_mma<<<MT * NT, 256>>>();

    dim3 gs(FOUT / 256, 8);
    stats_kernel<<<gs, 256>>>(NROW, FOUT);
    coef_kernel<<<(FOUT + 255) / 256, 256>>>(NROW, FOUT);
    bnq_kernel<<<2048, 256>>>(gamma, beta, abits, (float*)d_out,
                              NROW * FOUT, FOUT);
}

// round 5
// speedup vs baseline: 3.1013x; 1.0035x over previous
#include <cuda_runtime.h>
#include <cuda_fp16.h>
#include <math.h>
#include <stdint.h>

// Fixed problem shape (verified R1: x[8192,4096], W[4096,4096])
#define K_IN 4096
#define NROW 8192
#define FOUT 4096

#define BM 128
#define BN 256
#define BK 16
#define NCH (K_IN / BK)       // 256
#define MT (NROW / BM)        // 64
#define NT (FOUT / BN)        // 16
#define SSTRIDE 24            // smem row stride in fp16 (48B, conflict-free for ldmatrix)

// ---------------- device scratch ----------------
__device__ __half g_Ap[(size_t)NROW * (2 * K_IN)];  // [xh | xl], row stride 2*K_IN
__device__ __half g_Bp[(size_t)FOUT * K_IN];        // integer weight codes (exact fp16)
__device__ float g_G[(size_t)NROW * FOUT];
__device__ unsigned int g_maxbits;
__device__ float g_scale;
__device__ float g_psum[8][FOUT];
__device__ float g_psq[8][FOUT];
__device__ float g_mean[FOUT];
__device__ float g_rstd[FOUT];

// ---------------- helpers (sm_80-era PTX only: compiles at compute_100) ------
__device__ __forceinline__ uint32_t smem_u32(const void* p) {
    return (uint32_t)__cvta_generic_to_shared(p);
}
#define CP_ASYNC16(dst, src) \
    asm volatile("cp.async.cg.shared.global [%0], [%1], 16;" :: "r"(dst), "l"(src) : "memory")
#define CP_COMMIT() asm volatile("cp.async.commit_group;" ::: "memory")
#define CP_WAIT1()  asm volatile("cp.async.wait_group 1;" ::: "memory")
#define CP_WAIT0()  asm volatile("cp.async.wait_group 0;" ::: "memory")

__device__ __forceinline__ void ldm_x4(uint32_t* r, uint32_t addr) {
    asm volatile("ldmatrix.sync.aligned.m8n8.x4.shared.b16 {%0,%1,%2,%3}, [%4];"
                 : "=r"(r[0]), "=r"(r[1]), "=r"(r[2]), "=r"(r[3]) : "r"(addr));
}
__device__ __forceinline__ void mma_f16(float* d, const uint32_t* a, const uint32_t* b) {
    asm volatile(
        "mma.sync.aligned.m16n8k16.row.col.f32.f16.f16.f32 "
        "{%0,%1,%2,%3}, {%4,%5,%6,%7}, {%8,%9}, {%0,%1,%2,%3};"
        : "+f"(d[0]), "+f"(d[1]), "+f"(d[2]), "+f"(d[3])
        : "r"(a[0]), "r"(a[1]), "r"(a[2]), "r"(a[3]), "r"(b[0]), "r"(b[1]));
}

// ---------------- small kernels ----------------
__global__ void init_kernel() { if (threadIdx.x == 0) g_maxbits = 0u; }

__global__ void maxabs_kernel(const float* __restrict__ W, int n) {
    float m = 0.f;
    for (int i = blockIdx.x * blockDim.x + threadIdx.x; i < n;
         i += gridDim.x * blockDim.x)
        m = fmaxf(m, fabsf(W[i]));
    #pragma unroll
    for (int o = 16; o > 0; o >>= 1)
        m = fmaxf(m, __shfl_xor_sync(0xffffffffu, m, o));
    if ((threadIdx.x & 31) == 0)
        atomicMax(&g_maxbits, __float_as_uint(m));
}

__global__ void scale_kernel(const int* __restrict__ wbits) {
    float nf = (float)((1 << ((*wbits) - 1)) - 1);
    g_scale = __fdiv_rn(__uint_as_float(g_maxbits), nf);
}

// W -> integer codes m (exact in fp16)
__global__ void quantm_kernel(const float* __restrict__ W,
                              const int* __restrict__ wbits) {
    float s = g_scale;
    float nf = (float)((1 << ((*wbits) - 1)) - 1);
    int t = blockIdx.x * blockDim.x + threadIdx.x;   // over FOUT*K_IN/4
    float4 w = ((const float4*)W)[t];
    float m0 = fminf(fmaxf(rintf(__fdiv_rn(w.x, s)), -nf), nf);
    float m1 = fminf(fmaxf(rintf(__fdiv_rn(w.y, s)), -nf), nf);
    float m2 = fminf(fmaxf(rintf(__fdiv_rn(w.z, s)), -nf), nf);
    float m3 = fminf(fmaxf(rintf(__fdiv_rn(w.w, s)), -nf), nf);
    __half2* d = (__half2*)&g_Bp[(size_t)t * 4];
    d[0] = __floats2half2_rn(m0, m1);
    d[1] = __floats2half2_rn(m2, m3);
}

// x -> [xh | xl] fp16 (row stride 2*K_IN); residual <= 2^-24 |x|
__global__ void splitx_kernel(const float* __restrict__ x) {
    int t = blockIdx.x * blockDim.x + threadIdx.x;   // over NROW*K_IN/4
    float4 v = ((const float4*)x)[t];
    int row = t >> 10;                 // / (K_IN/4)
    int col = (t & 1023) << 2;
    __half h0 = __float2half_rn(v.x);
    __half h1 = __float2half_rn(v.y);
    __half h2 = __float2half_rn(v.z);
    __half h3 = __float2half_rn(v.w);
    __half l0 = __float2half_rn(v.x - __half2float(h0));
    __half l1 = __float2half_rn(v.y - __half2float(h1));
    __half l2 = __float2half_rn(v.z - __half2float(h2));
    __half l3 = __float2half_rn(v.w - __half2float(h3));
    __half2* dh = (__half2*)&g_Ap[(size_t)row * (2 * K_IN) + col];
    __half2* dl = (__half2*)&g_Ap[(size_t)row * (2 * K_IN) + K_IN + col];
    dh[0] = __half2{h0, h1}; dh[1] = __half2{h2, h3};
    dl[0] = __half2{l0, l1}; dl[1] = __half2{l2, l3};
}

// ---------------- GEMM: mma.sync fp16, 128x256 tile, warp 64x64 ----------------
__global__ void __launch_bounds__(256) gemm_mma() {
    __shared__ __half sAh[2][BM * SSTRIDE];   // 12,288 B
    __shared__ __half sAl[2][BM * SSTRIDE];   // 12,288 B
    __shared__ __half sB[2][BN * SSTRIDE];    // 24,576 B  (total 48 KB)

    const int tid = threadIdx.x;
    const int wid = tid >> 5;
    const int lane = tid & 31;
    const int wm = wid & 1;          // 2 warp rows (64 rows each)
    const int wn = wid >> 1;         // 4 warp cols (64 cols each)

    // supertile raster: 16 tm x 16 tn per supertile (4 supertiles)
    const int cid = blockIdx.x;
    const int sup = cid >> 8;
    const int rem = cid & 255;
    const int tm = (sup << 4) | (rem & 15);   // 0..63
    const int tn = rem >> 4;                  // 0..15

    float acc[4][8][4];
    #pragma unroll
    for (int a = 0; a < 4; a++)
        #pragma unroll
        for (int b = 0; b < 8; b++)
            #pragma unroll
            for (int c = 0; c < 4; c++) acc[a][b][c] = 0.f;

    // loaders: A rows 128x32B -> 1 cp.async/thread each; B rows 256x32B -> 2/thread
    const int lr = tid >> 1;
    const int lc = tid & 1;
    const char* gAh = (const char*)(g_Ap + (size_t)(tm * BM + lr) * (2 * K_IN)) + lc * 16;
    const char* gAl = gAh + (size_t)K_IN * 2;
    const char* gB0 = (const char*)(g_Bp + (size_t)(tn * BN + lr) * K_IN) + lc * 16;
    const char* gB1 = (const char*)(g_Bp + (size_t)(tn * BN + 128 + lr) * K_IN) + lc * 16;
    const uint32_t dstA = (uint32_t)(lr * SSTRIDE * 2 + lc * 16);
    const uint32_t dstB1 = (uint32_t)((128 + lr) * SSTRIDE * 2 + lc * 16);
    const uint32_t sAh_u[2] = { smem_u32(sAh[0]), smem_u32(sAh[1]) };
    const uint32_t sAl_u[2] = { smem_u32(sAl[0]), smem_u32(sAl[1]) };
    const uint32_t sB_u[2]  = { smem_u32(sB[0]),  smem_u32(sB[1]) };

    // ldmatrix address components
    //   A x4: rows = base + (lane&15), k-half = lane>>4
    const uint32_t a_off = (uint32_t)(((wm * 64 + (lane & 15)) * SSTRIDE + (lane >> 4) * 8) * 2);
    //   B x4 (two n-tiles): rows = base + ((lane>>4)<<3) + (lane&7), k-half = (lane>>3)&1
    const uint32_t b_off = (uint32_t)(((wn * 64 + ((lane >> 4) << 3) + (lane & 7)) * SSTRIDE
                                       + ((lane >> 3) & 1) * 8) * 2);

    // prologue: stage 0
    CP_ASYNC16(sAh_u[0] + dstA, gAh);
    CP_ASYNC16(sAl_u[0] + dstA, gAl);
    CP_ASYNC16(sB_u[0] + dstA, gB0);
    CP_ASYNC16(sB_u[0] + dstB1, gB1);
    CP_COMMIT();

    for (int i = 0; i < NCH; i++) {
        const int b = i & 1;
        if (i + 1 < NCH) {
            const int nb = (i + 1) & 1;
            const size_t ko = (size_t)(i + 1) * BK * 2;   // bytes along K
            CP_ASYNC16(sAh_u[nb] + dstA, gAh + ko);
            CP_ASYNC16(sAl_u[nb] + dstA, gAl + ko);
            CP_ASYNC16(sB_u[nb] + dstA, gB0 + ko);
            CP_ASYNC16(sB_u[nb] + dstB1, gB1 + ko);
            CP_COMMIT();
            CP_WAIT1();
        } else {
            CP_WAIT0();
        }
        __syncthreads();

        uint32_t bf[8][2];
        #pragma unroll
        for (int p = 0; p < 4; p++) {
            uint32_t r[4];
            ldm_x4(r, sB_u[b] + b_off + (uint32_t)(p * 16 * SSTRIDE * 2));
            bf[2 * p][0] = r[0]; bf[2 * p][1] = r[1];
            bf[2 * p + 1][0] = r[2]; bf[2 * p + 1][1] = r[3];
        }
        uint32_t ah[4][4], al[4][4];
        #pragma unroll
        for (int mt = 0; mt < 4; mt++) {
            ldm_x4(ah[mt], sAh_u[b] + a_off + (uint32_t)(mt * 16 * SSTRIDE * 2));
            ldm_x4(al[mt], sAl_u[b] + a_off + (uint32_t)(mt * 16 * SSTRIDE * 2));
        }
        #pragma unroll
        for (int mt = 0; mt < 4; mt++)
            #pragma unroll
            for (int nt = 0; nt < 8; nt++) {
                mma_f16(acc[mt][nt], ah[mt], bf[nt]);
                mma_f16(acc[mt][nt], al[mt], bf[nt]);
            }
        __syncthreads();
    }

    // epilogue: scale by s, float2 stores
    const float s = g_scale;
    const int rbase = tm * BM + wm * 64 + (lane >> 2);
    const int cbase = tn * BN + wn * 64 + 2 * (lane & 3);
    #pragma unroll
    for (int mt = 0; mt < 4; mt++) {
        #pragma unroll
        for (int nt = 0; nt < 8; nt++) {
            const int rr = rbase + mt * 16;
            const int cc = cbase + nt * 8;
            float2 v0 = { acc[mt][nt][0] * s, acc[mt][nt][1] * s };
            float2 v1 = { acc[mt][nt][2] * s, acc[mt][nt][3] * s };
            *(float2*)&g_G[(size_t)rr * FOUT + cc] = v0;
            *(float2*)&g_G[(size_t)(rr + 8) * FOUT + cc] = v1;
        }
    }
}

// ---------------- stats + BN + act-quant (verified R1) ----------------
__global__ void stats_kernel(int Nr, int Nc) {
    int c  = blockIdx.x * blockDim.x + threadIdx.x;
    int rb = blockIdx.y;
    int rows = Nr >> 3;
    const float* p = g_G + (size_t)(rb * rows) * Nc + c;
    float s0 = 0.f, s1 = 0.f, q0 = 0.f, q1 = 0.f;
    for (int r = 0; r < rows; r += 2) {
        float v0 = p[0];
        float v1 = p[Nc];
        p += 2 * (size_t)Nc;
        s0 += v0; q0 = fmaf(v0, v0, q0);
        s1 += v1; q1 = fmaf(v1, v1, q1);
    }
    g_psum[rb][c] = s0 + s1;
    g_psq[rb][c]  = q0 + q1;
}

__global__ void coef_kernel(int Nr, int Nc) {
    int c = blockIdx.x * blockDim.x + threadIdx.x;
    if (c >= Nc) return;
    float s = 0.f, q = 0.f;
    #pragma unroll
    for (int i = 0; i < 8; i++) { s += g_psum[i][c]; q += g_psq[i][c]; }
    float mean = s / (float)Nr;
    float ex2  = q / (float)Nr;
    float var  = ex2 - mean * mean;
    g_mean[c] = mean;
    g_rstd[c] = (float)(1.0 / sqrt((double)var + 1e-5));
}

__global__ void bnq_kernel(const float* __restrict__ gamma,
                           const float* __restrict__ beta,
                           const int* __restrict__ abits,
                           float* __restrict__ out, int total, int Nc) {
    float na = (float)((1 << (*abits)) - 1);
    for (int i = blockIdx.x * blockDim.x + threadIdx.x; i < total;
         i += gridDim.x * blockDim.x) {
        int c = i % Nc;
        float g = g_G[i];
        float y = gamma[c] * (g - g_mean[c]) * g_rstd[c] + beta[c];
        float yc = fminf(fmaxf(y, 0.f), 1.f);
        float q = __fdiv_rn(rintf(yc * na), na);
        out[i] = yc + (q - yc);
    }
}

// ---------------- launch ----------------
extern "C" void kernel_launch(void* const* d_in, const int* in_sizes, int n_in,
                              void* d_out, int out_size) {
    const float* x     = (const float*)d_in[0];
    const float* W     = (const float*)d_in[1];
    const float* gamma = (const float*)d_in[2];
    const float* beta  = (const float*)d_in[3];
    const int*   wbits = (const int*)d_in[4];
    const int*   abits = (const int*)d_in[5];

    init_kernel<<<1, 32>>>();
    maxabs_kernel<<<256, 256>>>(W, FOUT * K_IN);
    scale_kernel<<<1, 1>>>(wbits);
    quantm_kernel<<<(FOUT * K_IN / 4) / 256, 256>>>(W, wbits);
    splitx_kernel<<<(NROW * K_IN / 4) / 256, 256>>>(x);

    gemm_mma<<<MT * NT, 256>>>();

    dim3 gs(FOUT / 256, 8);
    stats_kernel<<<gs, 256>>>(NROW, FOUT);
    coef_kernel<<<(FOUT + 255) / 256, 256>>>(NROW, FOUT);
    bnq_kernel<<<2048, 256>>>(gamma, beta, abits, (float*)d_out,
                              NROW * FOUT, FOUT);
}

// round 10
// speedup vs baseline: 4.3350x; 1.3978x over previous
#include <cuda_runtime.h>
#include <math.h>
#include <stdint.h>

// Fixed problem shape (verified R1: x[8192,4096], W[4096,4096])
#define K_IN 4096
#define NROW 8192
#define FOUT 4096

#define BM 128
#define BN 128
#define BKB 64                // K bytes per stage (64 int8)
#define NCH (K_IN / BKB)      // 64
#define MT (NROW / BM)        // 64
#define NT (FOUT / BN)        // 32
#define MATB (BM * 64)        // 8192 B per matrix per stage
#define INV254 (1.f / 254.f)

// XOR swizzle: 16B-chunk index within a 64B row, keyed by row
#define SWZ(row, c16) (((c16) ^ (((row) >> 1) & 3)) << 4)

// ---------------- device scratch ----------------
__device__ int8_t g_Ad[(size_t)NROW * (3 * K_IN)];  // [X1 | X2 | X3] per row
__device__ int8_t g_Bq[(size_t)FOUT * K_IN];        // weight codes m
__device__ float g_G[(size_t)NROW * FOUT];
__device__ float g_sn[NROW];                        // per-row scale s_n
__device__ float g_inv[NROW];                       // 127 / rowmax
__device__ unsigned int g_maxbits;
__device__ float g_scale;
__device__ float g_psum[8][FOUT];
__device__ float g_psq[8][FOUT];
__device__ float g_mean[FOUT];
__device__ float g_rstd[FOUT];

// ---------------- helpers (sm_80-era PTX: legal at compute_100) ----------------
__device__ __forceinline__ uint32_t smem_u32(const void* p) {
    return (uint32_t)__cvta_generic_to_shared(p);
}
#define CP_ASYNC16(dst, src) \
    asm volatile("cp.async.cg.shared.global [%0], [%1], 16;" :: "r"(dst), "l"(src) : "memory")
#define CP_COMMIT() asm volatile("cp.async.commit_group;" ::: "memory")
#define CP_WAIT1()  asm volatile("cp.async.wait_group 1;" ::: "memory")
#define CP_WAIT0()  asm volatile("cp.async.wait_group 0;" ::: "memory")

__device__ __forceinline__ void ldm_x4(uint32_t* r, uint32_t addr) {
    asm volatile("ldmatrix.sync.aligned.m8n8.x4.shared.b16 {%0,%1,%2,%3}, [%4];"
                 : "=r"(r[0]), "=r"(r[1]), "=r"(r[2]), "=r"(r[3]) : "r"(addr));
}
__device__ __forceinline__ void imma(int* d, const uint32_t* a, uint32_t b0, uint32_t b1) {
    asm volatile(
        "mma.sync.aligned.m16n8k32.row.col.s32.s8.s8.s32 "
        "{%0,%1,%2,%3}, {%4,%5,%6,%7}, {%8,%9}, {%0,%1,%2,%3};"
        : "+r"(d[0]), "+r"(d[1]), "+r"(d[2]), "+r"(d[3])
        : "r"(a[0]), "r"(a[1]), "r"(a[2]), "r"(a[3]), "r"(b0), "r"(b1));
}

// ---------------- small kernels ----------------
__global__ void init_kernel() { if (threadIdx.x == 0) g_maxbits = 0u; }

__global__ void maxabs_kernel(const float* __restrict__ W, int n) {
    float m = 0.f;
    for (int i = blockIdx.x * blockDim.x + threadIdx.x; i < n;
         i += gridDim.x * blockDim.x)
        m = fmaxf(m, fabsf(W[i]));
    #pragma unroll
    for (int o = 16; o > 0; o >>= 1)
        m = fmaxf(m, __shfl_xor_sync(0xffffffffu, m, o));
    if ((threadIdx.x & 31) == 0)
        atomicMax(&g_maxbits, __float_as_uint(m));
}

__global__ void scale_kernel(const int* __restrict__ wbits) {
    float nf = (float)((1 << ((*wbits) - 1)) - 1);
    g_scale = __fdiv_rn(__uint_as_float(g_maxbits), nf);
}

// W -> integer codes m (int8)
__global__ void quantm_kernel(const float* __restrict__ W,
                              const int* __restrict__ wbits) {
    float s = g_scale;
    float nf = (float)((1 << ((*wbits) - 1)) - 1);
    int t = blockIdx.x * blockDim.x + threadIdx.x;   // over FOUT*K_IN/4
    float4 w = ((const float4*)W)[t];
    float m0 = fminf(fmaxf(rintf(__fdiv_rn(w.x, s)), -nf), nf);
    float m1 = fminf(fmaxf(rintf(__fdiv_rn(w.y, s)), -nf), nf);
    float m2 = fminf(fmaxf(rintf(__fdiv_rn(w.z, s)), -nf), nf);
    float m3 = fminf(fmaxf(rintf(__fdiv_rn(w.w, s)), -nf), nf);
    char4 c = make_char4((char)(int)m0, (char)(int)m1, (char)(int)m2, (char)(int)m3);
    *(char4*)&g_Bq[(size_t)t * 4] = c;
}

// per-row max|x| -> s_n, inv
__global__ void rowscale_kernel(const float* __restrict__ x) {
    __shared__ float red[8];
    const int row = blockIdx.x;
    const int tid = threadIdx.x;
    const float4* p = (const float4*)(x + (size_t)row * K_IN);
    float m = 0.f;
    #pragma unroll
    for (int i = 0; i < 4; i++) {
        float4 v = p[tid + i * 256];
        m = fmaxf(m, fmaxf(fmaxf(fabsf(v.x), fabsf(v.y)),
                           fmaxf(fabsf(v.z), fabsf(v.w))));
    }
    #pragma unroll
    for (int o = 16; o > 0; o >>= 1)
        m = fmaxf(m, __shfl_xor_sync(0xffffffffu, m, o));
    if ((tid & 31) == 0) red[tid >> 5] = m;
    __syncthreads();
    if (tid == 0) {
        float mm = red[0];
        #pragma unroll
        for (int i = 1; i < 8; i++) mm = fmaxf(mm, red[i]);
        g_sn[row]  = __fdiv_rn(mm, 127.f);
        g_inv[row] = __fdiv_rn(127.f, mm);
    }
}

// x -> three int8 digits: x ~= sn*X1 + s2*X2 + s3*X3, s2=sn/254, s3=s2/254
__global__ void digitize_kernel(const float* __restrict__ x) {
    int t = blockIdx.x * blockDim.x + threadIdx.x;   // over NROW*K_IN/4
    int row = t >> 10;                 // / (K_IN/4)
    int col = (t & 1023) << 2;
    float4 v = ((const float4*)x)[t];
    const float sn = g_sn[row];
    const float inv = g_inv[row];
    const float s2 = sn * INV254;
    const float inv2 = inv * 254.f;
    const float inv3 = inv2 * 254.f;
    float X1[4], X2[4], X3[4];
    float e[4] = {v.x, v.y, v.z, v.w};
    #pragma unroll
    for (int i = 0; i < 4; i++) {
        float d1 = fminf(fmaxf(rintf(e[i] * inv), -127.f), 127.f);
        float r1 = fmaf(-d1, sn, e[i]);
        float d2 = fminf(fmaxf(rintf(r1 * inv2), -127.f), 127.f);
        float r2 = fmaf(-d2, s2, r1);
        float d3 = fminf(fmaxf(rintf(r2 * inv3), -127.f), 127.f);
        X1[i] = d1; X2[i] = d2; X3[i] = d3;
    }
    char4 c1 = make_char4((char)(int)X1[0], (char)(int)X1[1],
                          (char)(int)X1[2], (char)(int)X1[3]);
    char4 c2 = make_char4((char)(int)X2[0], (char)(int)X2[1],
                          (char)(int)X2[2], (char)(int)X2[3]);
    char4 c3 = make_char4((char)(int)X3[0], (char)(int)X3[1],
                          (char)(int)X3[2], (char)(int)X3[3]);
    *(char4*)&g_Ad[(size_t)row * (3 * K_IN) + col] = c1;
    *(char4*)&g_Ad[(size_t)row * (3 * K_IN) + K_IN + col] = c2;
    *(char4*)&g_Ad[(size_t)row * (3 * K_IN) + 2 * K_IN + col] = c3;
}

// ------- GEMM kernel 1: digits 1+2.  g_G = s*(sn*G1 + s2*G2) -------
__global__ void __launch_bounds__(256) gemm_imma2() {
    __shared__ char sbuf[2][3][MATB];    // [stage][X1|X2|B] = 48 KB

    const int tid = threadIdx.x;
    const int wid = tid >> 5;
    const int lane = tid & 31;
    const int wm = wid & 1;
    const int wn = wid >> 1;

    const int cid = blockIdx.x;
    const int sup = cid >> 8;
    const int rem = cid & 255;
    const int tm = ((sup & 3) << 4) | (rem & 15);
    const int tn = ((sup >> 2) << 4) | (rem >> 4);

    int acc1[4][4][4], acc2[4][4][4];
    #pragma unroll
    for (int a = 0; a < 4; a++)
        #pragma unroll
        for (int b = 0; b < 4; b++)
            #pragma unroll
            for (int c = 0; c < 4; c++) { acc1[a][b][c] = 0; acc2[a][b][c] = 0; }

    const char* gsrc[6];
    uint32_t doff[6];
    #pragma unroll
    for (int j = 0; j < 6; j++) {
        int id = j * 256 + tid;
        int mat = id >> 9;           // 0=X1, 1=X2, 2=B
        int r2 = id & 511;
        int row = r2 >> 2;
        int c16 = r2 & 3;
        if (mat == 0)
            gsrc[j] = (const char*)g_Ad + (size_t)(tm * BM + row) * (3 * K_IN) + c16 * 16;
        else if (mat == 1)
            gsrc[j] = (const char*)g_Ad + (size_t)(tm * BM + row) * (3 * K_IN) + K_IN + c16 * 16;
        else
            gsrc[j] = (const char*)g_Bq + (size_t)(tn * BN + row) * K_IN + c16 * 16;
        doff[j] = (uint32_t)(mat * MATB + row * 64 + SWZ(row, c16));
    }
    const uint32_t base_u[2] = { smem_u32(sbuf[0]), smem_u32(sbuf[1]) };

    #pragma unroll
    for (int j = 0; j < 6; j++) CP_ASYNC16(base_u[0] + doff[j], gsrc[j]);
    CP_COMMIT();

    for (int i = 0; i < NCH; i++) {
        const int b = i & 1;
        if (i + 1 < NCH) {
            const int nb = (i + 1) & 1;
            const size_t ko = (size_t)(i + 1) * BKB;
            #pragma unroll
            for (int j = 0; j < 6; j++)
                CP_ASYNC16(base_u[nb] + doff[j], gsrc[j] + ko);
            CP_COMMIT();
            CP_WAIT1();
        } else {
            CP_WAIT0();
        }
        __syncthreads();

        const uint32_t sA1 = base_u[b];
        const uint32_t sA2 = base_u[b] + MATB;
        const uint32_t sB  = base_u[b] + 2 * MATB;

        #pragma unroll
        for (int ks = 0; ks < 2; ks++) {
            uint32_t bf[4][2];
            #pragma unroll
            for (int g = 0; g < 2; g++) {
                const int brow = wn * 32 + g * 16 + ((lane >> 4) << 3) + (lane & 7);
                const int bc16 = ks * 2 + ((lane >> 3) & 1);
                uint32_t r[4];
                ldm_x4(r, sB + (uint32_t)(brow * 64 + SWZ(brow, bc16)));
                bf[2 * g][0] = r[0]; bf[2 * g][1] = r[1];
                bf[2 * g + 1][0] = r[2]; bf[2 * g + 1][1] = r[3];
            }
            #pragma unroll
            for (int mt = 0; mt < 4; mt++) {
                const int arow = wm * 64 + mt * 16 + (lane & 15);
                const int ac16 = ks * 2 + (lane >> 4);
                const uint32_t aoff = (uint32_t)(arow * 64 + SWZ(arow, ac16));
                uint32_t a1[4], a2[4];
                ldm_x4(a1, sA1 + aoff);
                ldm_x4(a2, sA2 + aoff);
                #pragma unroll
                for (int nt = 0; nt < 4; nt++) {
                    imma(acc1[mt][nt], a1, bf[nt][0], bf[nt][1]);
                    imma(acc2[mt][nt], a2, bf[nt][0], bf[nt][1]);
                }
            }
        }
        __syncthreads();
    }

    // epilogue: g_G = s*sn*G1 + s*s2*G2
    const float s = g_scale;
    const int rbase = tm * BM + wm * 64 + (lane >> 2);
    const int cbase = tn * BN + wn * 32 + 2 * (lane & 3);
    #pragma unroll
    for (int mt = 0; mt < 4; mt++) {
        const int r0 = rbase + mt * 16;
        const int r1 = r0 + 8;
        const float f10 = s * g_sn[r0];
        const float f20 = f10 * INV254;
        const float f11 = s * g_sn[r1];
        const float f21 = f11 * INV254;
        #pragma unroll
        for (int nt = 0; nt < 4; nt++) {
            const int cc = cbase + nt * 8;
            float2 v0, v1;
            v0.x = fmaf(f10, (float)acc1[mt][nt][0], f20 * (float)acc2[mt][nt][0]);
            v0.y = fmaf(f10, (float)acc1[mt][nt][1], f20 * (float)acc2[mt][nt][1]);
            v1.x = fmaf(f11, (float)acc1[mt][nt][2], f21 * (float)acc2[mt][nt][2]);
            v1.y = fmaf(f11, (float)acc1[mt][nt][3], f21 * (float)acc2[mt][nt][3]);
            *(float2*)&g_G[(size_t)r0 * FOUT + cc] = v0;
            *(float2*)&g_G[(size_t)r1 * FOUT + cc] = v1;
        }
    }
}

// ------- GEMM kernel 2: digit 3.  g_G += s*s3*G3 -------
__global__ void __launch_bounds__(256) gemm_imma1() {
    __shared__ char sbuf[2][2][MATB];    // [stage][X3|B] = 32 KB

    const int tid = threadIdx.x;
    const int wid = tid >> 5;
    const int lane = tid & 31;
    const int wm = wid & 1;
    const int wn = wid >> 1;

    const int cid = blockIdx.x;
    const int sup = cid >> 8;
    const int rem = cid & 255;
    const int tm = ((sup & 3) << 4) | (rem & 15);
    const int tn = ((sup >> 2) << 4) | (rem >> 4);

    int acc3[4][4][4];
    #pragma unroll
    for (int a = 0; a < 4; a++)
        #pragma unroll
        for (int b = 0; b < 4; b++)
            #pragma unroll
            for (int c = 0; c < 4; c++) acc3[a][b][c] = 0;

    // 1024 chunks per stage, 4 per thread
    const char* gsrc[4];
    uint32_t doff[4];
    #pragma unroll
    for (int j = 0; j < 4; j++) {
        int id = j * 256 + tid;
        int mat = id >> 9;           // 0=X3, 1=B
        int r2 = id & 511;
        int row = r2 >> 2;
        int c16 = r2 & 3;
        if (mat == 0)
            gsrc[j] = (const char*)g_Ad + (size_t)(tm * BM + row) * (3 * K_IN) + 2 * K_IN + c16 * 16;
        else
            gsrc[j] = (const char*)g_Bq + (size_t)(tn * BN + row) * K_IN + c16 * 16;
        doff[j] = (uint32_t)(mat * MATB + row * 64 + SWZ(row, c16));
    }
    const uint32_t base_u[2] = { smem_u32(sbuf[0]), smem_u32(sbuf[1]) };

    #pragma unroll
    for (int j = 0; j < 4; j++) CP_ASYNC16(base_u[0] + doff[j], gsrc[j]);
    CP_COMMIT();

    for (int i = 0; i < NCH; i++) {
        const int b = i & 1;
        if (i + 1 < NCH) {
            const int nb = (i + 1) & 1;
            const size_t ko = (size_t)(i + 1) * BKB;
            #pragma unroll
            for (int j = 0; j < 4; j++)
                CP_ASYNC16(base_u[nb] + doff[j], gsrc[j] + ko);
            CP_COMMIT();
            CP_WAIT1();
        } else {
            CP_WAIT0();
        }
        __syncthreads();

        const uint32_t sA3 = base_u[b];
        const uint32_t sB  = base_u[b] + MATB;

        #pragma unroll
        for (int ks = 0; ks < 2; ks++) {
            uint32_t bf[4][2];
            #pragma unroll
            for (int g = 0; g < 2; g++) {
                const int brow = wn * 32 + g * 16 + ((lane >> 4) << 3) + (lane & 7);
                const int bc16 = ks * 2 + ((lane >> 3) & 1);
                uint32_t r[4];
                ldm_x4(r, sB + (uint32_t)(brow * 64 + SWZ(brow, bc16)));
                bf[2 * g][0] = r[0]; bf[2 * g][1] = r[1];
                bf[2 * g + 1][0] = r[2]; bf[2 * g + 1][1] = r[3];
            }
            #pragma unroll
            for (int mt = 0; mt < 4; mt++) {
                const int arow = wm * 64 + mt * 16 + (lane & 15);
                const int ac16 = ks * 2 + (lane >> 4);
                uint32_t a3[4];
                ldm_x4(a3, sA3 + (uint32_t)(arow * 64 + SWZ(arow, ac16)));
                #pragma unroll
                for (int nt = 0; nt < 4; nt++)
                    imma(acc3[mt][nt], a3, bf[nt][0], bf[nt][1]);
            }
        }
        __syncthreads();
    }

    // epilogue: g_G += s*s3*G3
    const float s = g_scale;
    const int rbase = tm * BM + wm * 64 + (lane >> 2);
    const int cbase = tn * BN + wn * 32 + 2 * (lane & 3);
    #pragma unroll
    for (int mt = 0; mt < 4; mt++) {
        const int r0 = rbase + mt * 16;
        const int r1 = r0 + 8;
        const float f30 = ((s * g_sn[r0]) * INV254) * INV254;
        const float f31 = ((s * g_sn[r1]) * INV254) * INV254;
        #pragma unroll
        for (int nt = 0; nt < 4; nt++) {
            const int cc = cbase + nt * 8;
            float2 v0 = *(float2*)&g_G[(size_t)r0 * FOUT + cc];
            float2 v1 = *(float2*)&g_G[(size_t)r1 * FOUT + cc];
            v0.x = fmaf(f30, (float)acc3[mt][nt][0], v0.x);
            v0.y = fmaf(f30, (float)acc3[mt][nt][1], v0.y);
            v1.x = fmaf(f31, (float)acc3[mt][nt][2], v1.x);
            v1.y = fmaf(f31, (float)acc3[mt][nt][3], v1.y);
            *(float2*)&g_G[(size_t)r0 * FOUT + cc] = v0;
            *(float2*)&g_G[(size_t)r1 * FOUT + cc] = v1;
        }
    }
}

// ---------------- stats + BN + act-quant (verified R1) ----------------
__global__ void stats_kernel(int Nr, int Nc) {
    int c  = blockIdx.x * blockDim.x + threadIdx.x;
    int rb = blockIdx.y;
    int rows = Nr >> 3;
    const float* p = g_G + (size_t)(rb * rows) * Nc + c;
    float s0 = 0.f, s1 = 0.f, q0 = 0.f, q1 = 0.f;
    for (int r = 0; r < rows; r += 2) {
        float v0 = p[0];
        float v1 = p[Nc];
        p += 2 * (size_t)Nc;
        s0 += v0; q0 = fmaf(v0, v0, q0);
        s1 += v1; q1 = fmaf(v1, v1, q1);
    }
    g_psum[rb][c] = s0 + s1;
    g_psq[rb][c]  = q0 + q1;
}

__global__ void coef_kernel(int Nr, int Nc) {
    int c = blockIdx.x * blockDim.x + threadIdx.x;
    if (c >= Nc) return;
    float s = 0.f, q = 0.f;
    #pragma unroll
    for (int i = 0; i < 8; i++) { s += g_psum[i][c]; q += g_psq[i][c]; }
    float mean = s / (float)Nr;
    float ex2  = q / (float)Nr;
    float var  = ex2 - mean * mean;
    g_mean[c] = mean;
    g_rstd[c] = (float)(1.0 / sqrt((double)var + 1e-5));
}

__global__ void bnq_kernel(const float* __restrict__ gamma,
                           const float* __restrict__ beta,
                           const int* __restrict__ abits,
                           float* __restrict__ out, int total, int Nc) {
    float na = (float)((1 << (*abits)) - 1);
    for (int i = blockIdx.x * blockDim.x + threadIdx.x; i < total;
         i += gridDim.x * blockDim.x) {
        int c = i % Nc;
        float g = g_G[i];
        float y = gamma[c] * (g - g_mean[c]) * g_rstd[c] + beta[c];
        float yc = fminf(fmaxf(y, 0.f), 1.f);
        float q = __fdiv_rn(rintf(yc * na), na);
        out[i] = yc + (q - yc);
    }
}

// ---------------- launch ----------------
extern "C" void kernel_launch(void* const* d_in, const int* in_sizes, int n_in,
                              void* d_out, int out_size) {
    const float* x     = (const float*)d_in[0];
    const float* W     = (const float*)d_in[1];
    const float* gamma = (const float*)d_in[2];
    const float* beta  = (const float*)d_in[3];
    const int*   wbits = (const int*)d_in[4];
    const int*   abits = (const int*)d_in[5];

    init_kernel<<<1, 32>>>();
    maxabs_kernel<<<256, 256>>>(W, FOUT * K_IN);
    scale_kernel<<<1, 1>>>(wbits);
    quantm_kernel<<<(FOUT * K_IN / 4) / 256, 256>>>(W, wbits);
    rowscale_kernel<<<NROW, 256>>>(x);
    digitize_kernel<<<(NROW * K_IN / 4) / 256, 256>>>(x);

    gemm_imma2<<<MT * NT, 256>>>();
    gemm_imma1<<<MT * NT, 256>>>();

    dim3 gs(FOUT / 256, 8);
    stats_kernel<<<gs, 256>>>(NROW, FOUT);
    coef_kernel<<<(FOUT + 255) / 256, 256>>>(NROW, FOUT);
    bnq_kernel<<<2048, 256>>>(gamma, beta, abits, (float*)d_out,
                              NROW * FOUT, FOUT);
}

// round 11
// speedup vs baseline: 4.6381x; 1.0699x over previous
#include <cuda_runtime.h>
#include <math.h>
#include <stdint.h>

// Fixed problem shape (verified R1: x[8192,4096], W[4096,4096])
#define K_IN 4096
#define NROW 8192
#define FOUT 4096

#define BM 128
#define BN 128
#define BKB 64                // K bytes per stage (64 int8)
#define NCH (K_IN / BKB)      // 64
#define MT (NROW / BM)        // 64
#define NT (FOUT / BN)        // 32
#define MATB (BM * 64)        // 8192 B per matrix per stage
#define INV254 (1.f / 254.f)

// XOR swizzle: 16B-chunk index within a 64B row, keyed by row
#define SWZ(row, c16) (((c16) ^ (((row) >> 1) & 3)) << 4)

// ---------------- device scratch ----------------
__device__ int8_t g_Ad[(size_t)NROW * (3 * K_IN)];  // [X1 | X2 | X3] per row
__device__ int8_t g_Bq[(size_t)FOUT * K_IN];        // weight codes m
__device__ float g_G[(size_t)NROW * FOUT];
__device__ float g_sn[NROW];                        // per-row scale s_n
__device__ unsigned int g_maxbits;
__device__ float g_scale;
__device__ float g_psum2[MT][FOUT];                 // per-row-block partial sums
__device__ float g_psq2[MT][FOUT];
__device__ float g_mean[FOUT];
__device__ float g_rstd[FOUT];

// ---------------- helpers (sm_80-era PTX: legal at compute_100) ----------------
__device__ __forceinline__ uint32_t smem_u32(const void* p) {
    return (uint32_t)__cvta_generic_to_shared(p);
}
#define CP_ASYNC16(dst, src) \
    asm volatile("cp.async.cg.shared.global [%0], [%1], 16;" :: "r"(dst), "l"(src) : "memory")
#define CP_COMMIT() asm volatile("cp.async.commit_group;" ::: "memory")
#define CP_WAIT1()  asm volatile("cp.async.wait_group 1;" ::: "memory")
#define CP_WAIT0()  asm volatile("cp.async.wait_group 0;" ::: "memory")

__device__ __forceinline__ void ldm_x4(uint32_t* r, uint32_t addr) {
    asm volatile("ldmatrix.sync.aligned.m8n8.x4.shared.b16 {%0,%1,%2,%3}, [%4];"
                 : "=r"(r[0]), "=r"(r[1]), "=r"(r[2]), "=r"(r[3]) : "r"(addr));
}
__device__ __forceinline__ void imma(int* d, const uint32_t* a, uint32_t b0, uint32_t b1) {
    asm volatile(
        "mma.sync.aligned.m16n8k32.row.col.s32.s8.s8.s32 "
        "{%0,%1,%2,%3}, {%4,%5,%6,%7}, {%8,%9}, {%0,%1,%2,%3};"
        : "+r"(d[0]), "+r"(d[1]), "+r"(d[2]), "+r"(d[3])
        : "r"(a[0]), "r"(a[1]), "r"(a[2]), "r"(a[3]), "r"(b0), "r"(b1));
}

// ---------------- small kernels ----------------
__global__ void init_kernel() { if (threadIdx.x == 0) g_maxbits = 0u; }

__global__ void maxabs_kernel(const float* __restrict__ W, int n) {
    float m = 0.f;
    for (int i = blockIdx.x * blockDim.x + threadIdx.x; i < n;
         i += gridDim.x * blockDim.x)
        m = fmaxf(m, fabsf(W[i]));
    #pragma unroll
    for (int o = 16; o > 0; o >>= 1)
        m = fmaxf(m, __shfl_xor_sync(0xffffffffu, m, o));
    if ((threadIdx.x & 31) == 0)
        atomicMax(&g_maxbits, __float_as_uint(m));
}

__global__ void scale_kernel(const int* __restrict__ wbits) {
    float nf = (float)((1 << ((*wbits) - 1)) - 1);
    g_scale = __fdiv_rn(__uint_as_float(g_maxbits), nf);
}

// W -> integer codes m (int8)
__global__ void quantm_kernel(const float* __restrict__ W,
                              const int* __restrict__ wbits) {
    float s = g_scale;
    float nf = (float)((1 << ((*wbits) - 1)) - 1);
    int t = blockIdx.x * blockDim.x + threadIdx.x;   // over FOUT*K_IN/4
    float4 w = ((const float4*)W)[t];
    float m0 = fminf(fmaxf(rintf(__fdiv_rn(w.x, s)), -nf), nf);
    float m1 = fminf(fmaxf(rintf(__fdiv_rn(w.y, s)), -nf), nf);
    float m2 = fminf(fmaxf(rintf(__fdiv_rn(w.z, s)), -nf), nf);
    float m3 = fminf(fmaxf(rintf(__fdiv_rn(w.w, s)), -nf), nf);
    char4 c = make_char4((char)(int)m0, (char)(int)m1, (char)(int)m2, (char)(int)m3);
    *(char4*)&g_Bq[(size_t)t * 4] = c;
}

// Fused: per-row max + 3-digit int8 encoding (row stays in registers)
__global__ void rowdig_kernel(const float* __restrict__ x) {
    __shared__ float red[8];
    __shared__ float bc[2];
    const int row = blockIdx.x;
    const int tid = threadIdx.x;
    const float4* p = (const float4*)(x + (size_t)row * K_IN);
    float4 v[4];
    float m = 0.f;
    #pragma unroll
    for (int i = 0; i < 4; i++) {
        v[i] = p[tid + i * 256];
        m = fmaxf(m, fmaxf(fmaxf(fabsf(v[i].x), fabsf(v[i].y)),
                           fmaxf(fabsf(v[i].z), fabsf(v[i].w))));
    }
    #pragma unroll
    for (int o = 16; o > 0; o >>= 1)
        m = fmaxf(m, __shfl_xor_sync(0xffffffffu, m, o));
    if ((tid & 31) == 0) red[tid >> 5] = m;
    __syncthreads();
    if (tid == 0) {
        float mm = red[0];
        #pragma unroll
        for (int i = 1; i < 8; i++) mm = fmaxf(mm, red[i]);
        float sn = __fdiv_rn(mm, 127.f);
        float inv = __fdiv_rn(127.f, mm);
        g_sn[row] = sn;
        bc[0] = sn; bc[1] = inv;
    }
    __syncthreads();
    const float sn = bc[0];
    const float inv = bc[1];
    const float s2 = sn * INV254;
    const float inv2 = inv * 254.f;
    const float inv3 = inv2 * 254.f;
    #pragma unroll
    for (int i = 0; i < 4; i++) {
        const int col = (tid + i * 256) * 4;
        float e[4] = {v[i].x, v[i].y, v[i].z, v[i].w};
        float X1[4], X2[4], X3[4];
        #pragma unroll
        for (int j = 0; j < 4; j++) {
            float d1 = fminf(fmaxf(rintf(e[j] * inv), -127.f), 127.f);
            float r1 = fmaf(-d1, sn, e[j]);
            float d2 = fminf(fmaxf(rintf(r1 * inv2), -127.f), 127.f);
            float r2 = fmaf(-d2, s2, r1);
            float d3 = fminf(fmaxf(rintf(r2 * inv3), -127.f), 127.f);
            X1[j] = d1; X2[j] = d2; X3[j] = d3;
        }
        char4 c1 = make_char4((char)(int)X1[0], (char)(int)X1[1],
                              (char)(int)X1[2], (char)(int)X1[3]);
        char4 c2 = make_char4((char)(int)X2[0], (char)(int)X2[1],
                              (char)(int)X2[2], (char)(int)X2[3]);
        char4 c3 = make_char4((char)(int)X3[0], (char)(int)X3[1],
                              (char)(int)X3[2], (char)(int)X3[3]);
        *(char4*)&g_Ad[(size_t)row * (3 * K_IN) + col] = c1;
        *(char4*)&g_Ad[(size_t)row * (3 * K_IN) + K_IN + col] = c2;
        *(char4*)&g_Ad[(size_t)row * (3 * K_IN) + 2 * K_IN + col] = c3;
    }
}

// ------- GEMM kernel 1: digits 1+2.  g_G = s*(sn*G1 + s2*G2) -------
__global__ void __launch_bounds__(256) gemm_imma2() {
    __shared__ char sbuf[2][3][MATB];    // [stage][X1|X2|B] = 48 KB

    const int tid = threadIdx.x;
    const int wid = tid >> 5;
    const int lane = tid & 31;
    const int wm = wid & 1;
    const int wn = wid >> 1;

    const int cid = blockIdx.x;
    const int sup = cid >> 8;
    const int rem = cid & 255;
    const int tm = ((sup & 3) << 4) | (rem & 15);
    const int tn = ((sup >> 2) << 4) | (rem >> 4);

    int acc1[4][4][4], acc2[4][4][4];
    #pragma unroll
    for (int a = 0; a < 4; a++)
        #pragma unroll
        for (int b = 0; b < 4; b++)
            #pragma unroll
            for (int c = 0; c < 4; c++) { acc1[a][b][c] = 0; acc2[a][b][c] = 0; }

    const char* gsrc[6];
    uint32_t doff[6];
    #pragma unroll
    for (int j = 0; j < 6; j++) {
        int id = j * 256 + tid;
        int mat = id >> 9;           // 0=X1, 1=X2, 2=B
        int r2 = id & 511;
        int row = r2 >> 2;
        int c16 = r2 & 3;
        if (mat == 0)
            gsrc[j] = (const char*)g_Ad + (size_t)(tm * BM + row) * (3 * K_IN) + c16 * 16;
        else if (mat == 1)
            gsrc[j] = (const char*)g_Ad + (size_t)(tm * BM + row) * (3 * K_IN) + K_IN + c16 * 16;
        else
            gsrc[j] = (const char*)g_Bq + (size_t)(tn * BN + row) * K_IN + c16 * 16;
        doff[j] = (uint32_t)(mat * MATB + row * 64 + SWZ(row, c16));
    }
    const uint32_t base_u[2] = { smem_u32(sbuf[0]), smem_u32(sbuf[1]) };

    #pragma unroll
    for (int j = 0; j < 6; j++) CP_ASYNC16(base_u[0] + doff[j], gsrc[j]);
    CP_COMMIT();

    for (int i = 0; i < NCH; i++) {
        const int b = i & 1;
        if (i + 1 < NCH) {
            const int nb = (i + 1) & 1;
            const size_t ko = (size_t)(i + 1) * BKB;
            #pragma unroll
            for (int j = 0; j < 6; j++)
                CP_ASYNC16(base_u[nb] + doff[j], gsrc[j] + ko);
            CP_COMMIT();
            CP_WAIT1();
        } else {
            CP_WAIT0();
        }
        __syncthreads();

        const uint32_t sA1 = base_u[b];
        const uint32_t sA2 = base_u[b] + MATB;
        const uint32_t sB  = base_u[b] + 2 * MATB;

        #pragma unroll
        for (int ks = 0; ks < 2; ks++) {
            uint32_t bf[4][2];
            #pragma unroll
            for (int g = 0; g < 2; g++) {
                const int brow = wn * 32 + g * 16 + ((lane >> 4) << 3) + (lane & 7);
                const int bc16 = ks * 2 + ((lane >> 3) & 1);
                uint32_t r[4];
                ldm_x4(r, sB + (uint32_t)(brow * 64 + SWZ(brow, bc16)));
                bf[2 * g][0] = r[0]; bf[2 * g][1] = r[1];
                bf[2 * g + 1][0] = r[2]; bf[2 * g + 1][1] = r[3];
            }
            #pragma unroll
            for (int mt = 0; mt < 4; mt++) {
                const int arow = wm * 64 + mt * 16 + (lane & 15);
                const int ac16 = ks * 2 + (lane >> 4);
                const uint32_t aoff = (uint32_t)(arow * 64 + SWZ(arow, ac16));
                uint32_t a1[4], a2[4];
                ldm_x4(a1, sA1 + aoff);
                ldm_x4(a2, sA2 + aoff);
                #pragma unroll
                for (int nt = 0; nt < 4; nt++) {
                    imma(acc1[mt][nt], a1, bf[nt][0], bf[nt][1]);
                    imma(acc2[mt][nt], a2, bf[nt][0], bf[nt][1]);
                }
            }
        }
        __syncthreads();
    }

    // epilogue: g_G = s*sn*G1 + s*s2*G2
    const float s = g_scale;
    const int rbase = tm * BM + wm * 64 + (lane >> 2);
    const int cbase = tn * BN + wn * 32 + 2 * (lane & 3);
    #pragma unroll
    for (int mt = 0; mt < 4; mt++) {
        const int r0 = rbase + mt * 16;
        const int r1 = r0 + 8;
        const float f10 = s * g_sn[r0];
        const float f20 = f10 * INV254;
        const float f11 = s * g_sn[r1];
        const float f21 = f11 * INV254;
        #pragma unroll
        for (int nt = 0; nt < 4; nt++) {
            const int cc = cbase + nt * 8;
            float2 v0, v1;
            v0.x = fmaf(f10, (float)acc1[mt][nt][0], f20 * (float)acc2[mt][nt][0]);
            v0.y = fmaf(f10, (float)acc1[mt][nt][1], f20 * (float)acc2[mt][nt][1]);
            v1.x = fmaf(f11, (float)acc1[mt][nt][2], f21 * (float)acc2[mt][nt][2]);
            v1.y = fmaf(f11, (float)acc1[mt][nt][3], f21 * (float)acc2[mt][nt][3]);
            *(float2*)&g_G[(size_t)r0 * FOUT + cc] = v0;
            *(float2*)&g_G[(size_t)r1 * FOUT + cc] = v1;
        }
    }
}

// ------- GEMM kernel 2: digit 3.  g_G += s*s3*G3; fused BN stats partials -------
__global__ void __launch_bounds__(256) gemm_imma1() {
    __shared__ char sbuf[2][2][MATB];    // [stage][X3|B] = 32 KB
    __shared__ float red[8][4][16];      // cross-warp stats reduction (2 KB)

    const int tid = threadIdx.x;
    const int wid = tid >> 5;
    const int lane = tid & 31;
    const int wm = wid & 1;
    const int wn = wid >> 1;

    const int cid = blockIdx.x;
    const int sup = cid >> 8;
    const int rem = cid & 255;
    const int tm = ((sup & 3) << 4) | (rem & 15);
    const int tn = ((sup >> 2) << 4) | (rem >> 4);

    int acc3[4][4][4];
    #pragma unroll
    for (int a = 0; a < 4; a++)
        #pragma unroll
        for (int b = 0; b < 4; b++)
            #pragma unroll
            for (int c = 0; c < 4; c++) acc3[a][b][c] = 0;

    // 1024 chunks per stage, 4 per thread
    const char* gsrc[4];
    uint32_t doff[4];
    #pragma unroll
    for (int j = 0; j < 4; j++) {
        int id = j * 256 + tid;
        int mat = id >> 9;           // 0=X3, 1=B
        int r2 = id & 511;
        int row = r2 >> 2;
        int c16 = r2 & 3;
        if (mat == 0)
            gsrc[j] = (const char*)g_Ad + (size_t)(tm * BM + row) * (3 * K_IN) + 2 * K_IN + c16 * 16;
        else
            gsrc[j] = (const char*)g_Bq + (size_t)(tn * BN + row) * K_IN + c16 * 16;
        doff[j] = (uint32_t)(mat * MATB + row * 64 + SWZ(row, c16));
    }
    const uint32_t base_u[2] = { smem_u32(sbuf[0]), smem_u32(sbuf[1]) };

    #pragma unroll
    for (int j = 0; j < 4; j++) CP_ASYNC16(base_u[0] + doff[j], gsrc[j]);
    CP_COMMIT();

    for (int i = 0; i < NCH; i++) {
        const int b = i & 1;
        if (i + 1 < NCH) {
            const int nb = (i + 1) & 1;
            const size_t ko = (size_t)(i + 1) * BKB;
            #pragma unroll
            for (int j = 0; j < 4; j++)
                CP_ASYNC16(base_u[nb] + doff[j], gsrc[j] + ko);
            CP_COMMIT();
            CP_WAIT1();
        } else {
            CP_WAIT0();
        }
        __syncthreads();

        const uint32_t sA3 = base_u[b];
        const uint32_t sB  = base_u[b] + MATB;

        #pragma unroll
        for (int ks = 0; ks < 2; ks++) {
            uint32_t bf[4][2];
            #pragma unroll
            for (int g = 0; g < 2; g++) {
                const int brow = wn * 32 + g * 16 + ((lane >> 4) << 3) + (lane & 7);
                const int bc16 = ks * 2 + ((lane >> 3) & 1);
                uint32_t r[4];
                ldm_x4(r, sB + (uint32_t)(brow * 64 + SWZ(brow, bc16)));
                bf[2 * g][0] = r[0]; bf[2 * g][1] = r[1];
                bf[2 * g + 1][0] = r[2]; bf[2 * g + 1][1] = r[3];
            }
            #pragma unroll
            for (int mt = 0; mt < 4; mt++) {
                const int arow = wm * 64 + mt * 16 + (lane & 15);
                const int ac16 = ks * 2 + (lane >> 4);
                uint32_t a3[4];
                ldm_x4(a3, sA3 + (uint32_t)(arow * 64 + SWZ(arow, ac16)));
                #pragma unroll
                for (int nt = 0; nt < 4; nt++)
                    imma(acc3[mt][nt], a3, bf[nt][0], bf[nt][1]);
            }
        }
        __syncthreads();
    }

    // epilogue: g_G += s*s3*G3, with fused per-CTA column sum/sumsq
    const float s = g_scale;
    const int rbase = tm * BM + wm * 64 + (lane >> 2);
    const int cbase = tn * BN + wn * 32 + 2 * (lane & 3);
    float cs[4][2], cq[4][2];
    #pragma unroll
    for (int nt = 0; nt < 4; nt++) {
        cs[nt][0] = 0.f; cs[nt][1] = 0.f;
        cq[nt][0] = 0.f; cq[nt][1] = 0.f;
    }
    #pragma unroll
    for (int mt = 0; mt < 4; mt++) {
        const int r0 = rbase + mt * 16;
        const int r1 = r0 + 8;
        const float f30 = ((s * g_sn[r0]) * INV254) * INV254;
        const float f31 = ((s * g_sn[r1]) * INV254) * INV254;
        #pragma unroll
        for (int nt = 0; nt < 4; nt++) {
            const int cc = cbase + nt * 8;
            float2 v0 = *(float2*)&g_G[(size_t)r0 * FOUT + cc];
            float2 v1 = *(float2*)&g_G[(size_t)r1 * FOUT + cc];
            v0.x = fmaf(f30, (float)acc3[mt][nt][0], v0.x);
            v0.y = fmaf(f30, (float)acc3[mt][nt][1], v0.y);
            v1.x = fmaf(f31, (float)acc3[mt][nt][2], v1.x);
            v1.y = fmaf(f31, (float)acc3[mt][nt][3], v1.y);
            *(float2*)&g_G[(size_t)r0 * FOUT + cc] = v0;
            *(float2*)&g_G[(size_t)r1 * FOUT + cc] = v1;
            cs[nt][0] += v0.x + v1.x;   cs[nt][1] += v0.y + v1.y;
            cq[nt][0] = fmaf(v0.x, v0.x, fmaf(v1.x, v1.x, cq[nt][0]));
            cq[nt][1] = fmaf(v0.y, v0.y, fmaf(v1.y, v1.y, cq[nt][1]));
        }
    }
    // reduce over the 8 threads (stride 4) sharing the same columns
    #pragma unroll
    for (int o = 16; o >= 4; o >>= 1) {
        #pragma unroll
        for (int nt = 0; nt < 4; nt++) {
            cs[nt][0] += __shfl_down_sync(0xffffffffu, cs[nt][0], o);
            cs[nt][1] += __shfl_down_sync(0xffffffffu, cs[nt][1], o);
            cq[nt][0] += __shfl_down_sync(0xffffffffu, cq[nt][0], o);
            cq[nt][1] += __shfl_down_sync(0xffffffffu, cq[nt][1], o);
        }
    }
    if (lane < 4) {
        #pragma unroll
        for (int nt = 0; nt < 4; nt++) {
            red[wid][lane][nt * 2]     = cs[nt][0];
            red[wid][lane][nt * 2 + 1] = cs[nt][1];
            red[wid][lane][8 + nt * 2]     = cq[nt][0];
            red[wid][lane][8 + nt * 2 + 1] = cq[nt][1];
        }
    }
    __syncthreads();
    if (wm == 0 && lane < 4) {
        // combine with partner warp (wid+1), write global partials
        const int col0 = tn * BN + wn * 32 + 2 * lane;
        #pragma unroll
        for (int nt = 0; nt < 4; nt++) {
            #pragma unroll
            for (int h = 0; h < 2; h++) {
                float ssum = red[wid][lane][nt * 2 + h] + red[wid + 1][lane][nt * 2 + h];
                float qsum = red[wid][lane][8 + nt * 2 + h] + red[wid + 1][lane][8 + nt * 2 + h];
                g_psum2[tm][col0 + nt * 8 + h] = ssum;
                g_psq2[tm][col0 + nt * 8 + h] = qsum;
            }
        }
    }
}

// ---------------- coef + BN + act-quant ----------------
__global__ void coef_kernel(int Nr, int Nc) {
    int c = blockIdx.x * blockDim.x + threadIdx.x;
    if (c >= Nc) return;
    float s = 0.f, q = 0.f;
    #pragma unroll 8
    for (int i = 0; i < MT; i++) { s += g_psum2[i][c]; q += g_psq2[i][c]; }
    float mean = s / (float)Nr;
    float ex2  = q / (float)Nr;
    float var  = ex2 - mean * mean;
    g_mean[c] = mean;
    g_rstd[c] = (float)(1.0 / sqrt((double)var + 1e-5));
}

__global__ void bnq_kernel(const float* __restrict__ gamma,
                           const float* __restrict__ beta,
                           const int* __restrict__ abits,
                           float* __restrict__ out, int total, int Nc) {
    float na = (float)((1 << (*abits)) - 1);
    for (int i = blockIdx.x * blockDim.x + threadIdx.x; i < total;
         i += gridDim.x * blockDim.x) {
        int c = i % Nc;
        float g = g_G[i];
        float y = gamma[c] * (g - g_mean[c]) * g_rstd[c] + beta[c];
        float yc = fminf(fmaxf(y, 0.f), 1.f);
        float q = __fdiv_rn(rintf(yc * na), na);
        out[i] = yc + (q - yc);
    }
}

// ---------------- launch ----------------
extern "C" void kernel_launch(void* const* d_in, const int* in_sizes, int n_in,
                              void* d_out, int out_size) {
    const float* x     = (const float*)d_in[0];
    const float* W     = (const float*)d_in[1];
    const float* gamma = (const float*)d_in[2];
    const float* beta  = (const float*)d_in[3];
    const int*   wbits = (const int*)d_in[4];
    const int*   abits = (const int*)d_in[5];

    init_kernel<<<1, 32>>>();
    maxabs_kernel<<<256, 256>>>(W, FOUT * K_IN);
    scale_kernel<<<1, 1>>>(wbits);
    quantm_kernel<<<(FOUT * K_IN / 4) / 256, 256>>>(W, wbits);
    rowdig_kernel<<<NROW, 256>>>(x);

    gemm_imma2<<<MT * NT, 256>>>();
    gemm_imma1<<<MT * NT, 256>>>();

    coef_kernel<<<(FOUT + 255) / 256, 256>>>(NROW, FOUT);
    bnq_kernel<<<2048, 256>>>(gamma, beta, abits, (float*)d_out,
                              NROW * FOUT, FOUT);
}